// round 16
// baseline (speedup 1.0000x reference)
#include <cuda_runtime.h>

#define NBINS   256
#define NSLOT   32
#define H_TPB   1024
#define H_BLK   148
#define J_BYTES (NBINS * NBINS * 2)      // 128 KB joint histogram (u16 cells)
#define CQ      14                       // px/CTA/chunk = 57344 < 65536

__device__ int   g_slots[2][NSLOT][NBINS];   // zero-init; last k1 block re-zeroes
__device__ float g_pxmap[NBINS];
__device__ int   g_done;

extern __shared__ unsigned int s_J[];

__device__ __forceinline__ int bin_of(float x) {
    return min(max((int)(x * 256.0f), 0), NBINS - 1);
}

__device__ __forceinline__ void jinc(int b, int c) {
    atomicAdd(&s_J[(b << 7) + (c >> 1)], 1u << ((c & 1) << 4));
}

// luma of rescaled pixel, folded: y = SC*(0.299r+0.587g+0.114b) + SC
__device__ __forceinline__ float luma(float r, float g, float b, float SC) {
    float dot = fmaf(0.299f, r, fmaf(0.587f, g, 0.114f * b));
    return fmaf(SC, dot, SC);
}

// ---------------------------------------------------------------------------
// k1: joint histogram + x spill to out + (last block) slot-reduce/CDF/pxmap.
// ---------------------------------------------------------------------------
__global__ void __launch_bounds__(H_TPB, 1) k1_hist(const float* __restrict__ src,
                                                    const float* __restrict__ tgt,
                                                    float* __restrict__ out, int n) {
    __shared__ int   sha[NBINS], shb[NBINS];
    __shared__ int   is_last;

    const int t    = threadIdx.x;
    const int nth  = gridDim.x * H_TPB;
    const int gtid = blockIdx.x * H_TPB + t;
    const int nq   = n >> 2;
    const float SC = 127.0f / 255.0f;
    const int CHUNK_Q = nth * CQ;

    if (t < NBINS) { sha[t] = 0; shb[t] = 0; }

    const float4* s4 = (const float4*)src;
    const float4* t4 = (const float4*)tgt;
    float4*       o4 = (float4*)out;

    for (int cbase = 0; cbase < nq; cbase += CHUNK_Q) {
        const int cend = min(cbase + CHUNK_Q, nq);

        {   // zero J
            uint4* z = (uint4*)s_J;
            #pragma unroll
            for (int i = 0; i < (NBINS * NBINS / 2 / 4) / H_TPB; ++i)
                z[t + i * H_TPB] = make_uint4(0, 0, 0, 0);
        }
        __syncthreads();

        for (int q = cbase + gtid; q < cend; q += nth) {
            float4 a  = s4[3 * q + 0];
            float4 b  = s4[3 * q + 1];
            float4 c  = s4[3 * q + 2];
            float4 ta = t4[3 * q + 0];
            float4 tb = t4[3 * q + 1];
            float4 tc = t4[3 * q + 2];

            float x0 = fmaf(a.x, SC, SC), x1 = fmaf(a.w, SC, SC);
            float x2 = fmaf(b.z, SC, SC), x3 = fmaf(c.y, SC, SC);
            o4[q] = make_float4(x0, x1, x2, x3);

            float y0 = luma(ta.x, ta.y, ta.z, SC);
            float y1 = luma(ta.w, tb.x, tb.y, SC);
            float y2 = luma(tb.z, tb.w, tc.x, SC);
            float y3 = luma(tc.y, tc.z, tc.w, SC);

            jinc(bin_of(x0), bin_of(y0));       // ONE atomic per pixel
            jinc(bin_of(x1), bin_of(y1));
            jinc(bin_of(x2), bin_of(y2));
            jinc(bin_of(x3), bin_of(y3));
        }
        __syncthreads();

        // ---- marginals ----
        if (t < NBINS) {
            const unsigned int* row = s_J + (t << 7);
            unsigned int s = 0;
            #pragma unroll 8
            for (int i = 0; i < 128; ++i) {
                unsigned int w = row[(i + t) & 127];   // +t swizzle: conflict-free
                s += (w & 0xffffu) + (w >> 16);
            }
            sha[t] += (int)s;
        } else if (t < 3 * NBINS) {
            const int u    = t - NBINS;
            const int c    = u >> 1;
            const int half = u & 1;
            const int widx = c >> 1;
            const int shft = (c & 1) << 4;
            unsigned int s = 0;
            #pragma unroll 8
            for (int b = half * 128; b < half * 128 + 128; ++b) {
                unsigned int w = s_J[(b << 7) + widx];
                s += (w >> shft) & 0xffffu;
            }
            if (s) atomicAdd(&shb[c], (int)s);
        }
        __syncthreads();
    }

    // Tail pixels (n % 4): at most 3, straight to global slot 0.
    const int tidx = 4 * nq + gtid;
    if (tidx < n) {
        float x = fmaf(src[3 * tidx], SC, SC);
        out[tidx] = x;
        atomicAdd(&g_slots[0][0][bin_of(x)], 1);
        float y = luma(tgt[3 * tidx + 0], tgt[3 * tidx + 1], tgt[3 * tidx + 2], SC);
        atomicAdd(&g_slots[1][0][bin_of(y)], 1);
    }

    // ---- slotted flush ----
    {
        const int slot = blockIdx.x & (NSLOT - 1);
        if (t < NBINS) {
            int va = sha[t];
            if (va) atomicAdd(&g_slots[0][slot][t], va);
        } else if (t < 2 * NBINS) {
            int vb = shb[t - NBINS];
            if (vb) atomicAdd(&g_slots[1][slot][t - NBINS], vb);
        }
    }

    // release flushes, then count this block done
    __threadfence();
    __syncthreads();
    if (t == 0)
        is_last = (atomicAdd(&g_done, 1) == (int)gridDim.x - 1);
    __syncthreads();
    if (!is_last) return;

    // ======== last block only: reduce slots, CDF, pxmap ========
    __threadfence();   // acquire: all other blocks' REDs visible
    __shared__ float fsv2[NBINS], ct[NBINS];
    if (t < NBINS) {
        float v = (float)((double)t * (1.0 / 255.0));  // np.arange semantics
        fsv2[t] = fminf(fmaxf(v, 0.0f), 1.0f);
        int suma = 0, sumb = 0;
        #pragma unroll
        for (int s = 0; s < NSLOT; ++s) {
            suma += g_slots[0][s][t];
            sumb += g_slots[1][s][t];
            g_slots[0][s][t] = 0;        // safe: all flushes counted above
            g_slots[1][s][t] = 0;
        }
        sha[t] = suma;
        shb[t] = sumb;
    }
    __syncthreads();
    #pragma unroll
    for (int off = 1; off < NBINS; off <<= 1) {
        int aself = 0, bself = 0, aprev = 0, bprev = 0;
        if (t < NBINS) {
            aself = sha[t]; bself = shb[t];
            if (t >= off) { aprev = sha[t - off]; bprev = shb[t - off]; }
        }
        __syncthreads();
        if (t < NBINS) { sha[t] = aself + aprev; shb[t] = bself + bprev; }
        __syncthreads();
    }
    if (t < NBINS) {
        int mint = shb[0];
        ct[t] = (float)(shb[t] - mint) / (float)(n - 1);      // cdftgt
    }
    __syncthreads();
    if (t < NBINS) {
        int mins = sha[0];
        float x = (float)(sha[t] - mins) / (float)(n - 1);    // cdfsrc
        int lo = 0, hi = NBINS - 1;
        while (lo < hi) { int mid = (lo + hi) >> 1; if (ct[mid] > x) hi = mid; else lo = mid + 1; }
        int ind1 = lo;
        int ind0 = max(ind1 - 1, 0);
        float dx0 = ct[ind0], dx1 = ct[ind1];
        float dy0 = fsv2[ind0], dy1 = fsv2[ind1];
        float dnm = dx1 - dx0;
        float sd  = (dnm == 0.0f) ? 1.0f : dnm;
        float interp = dy0 + (dy1 - dy0) * (x - dx0) / sd;
        float res = (x <= ct[0]) ? fsv2[0]
                  : ((x >= ct[NBINS - 1]) ? fsv2[NBINS - 1] : interp);
        g_pxmap[t] = res;
    }
    __syncthreads();
    if (t == 0) {
        g_done = 0;          // replay reset (all blocks already counted)
        __threadfence();
    }
}

// ---------------------------------------------------------------------------
// k3: apply via direct segment index (no search) + folded-clip float2 table.
//   result = clamp(fmaf(A*K, x, B*K-1), -1, K-1),  K = 255/127.
// Segment misselection only within ~1.5e-7 of a breakpoint; the map is
// continuous there, so output error ~1e-7 << 1e-3 tolerance.
// ---------------------------------------------------------------------------
__global__ void __launch_bounds__(256, 6) k3_apply(float* __restrict__ io, int n) {
    __shared__ float2 C[NBINS];
    __shared__ float  fsv[NBINS], pmS[NBINS];
    const int t = threadIdx.x;
    const float K = 255.0f / 127.0f;

    {
        float v = (float)((double)t * (1.0 / 255.0));
        fsv[t] = fminf(fmaxf(v, 0.0f), 1.0f);
        pmS[t] = g_pxmap[t];
    }
    __syncthreads();
    if (t > 0) {
        float d = fsv[t] - fsv[t - 1];             // strictly > 0
        float a = (pmS[t] - pmS[t - 1]) / d;
        float b = pmS[t - 1] - a * fsv[t - 1];
        C[t] = make_float2(a * K, b * K - 1.0f);
    }
    __syncthreads();

    const float LO = -1.0f;
    const float HI = 255.0f / 127.0f - 1.0f;       // clip(.,0,1)*K-1 upper bound

    float4* io4 = (float4*)io;
    const int nq = n >> 2;
    const int stride = gridDim.x * blockDim.x;

    for (int q = blockIdx.x * blockDim.x + t; q < nq; q += stride) {
        float4 v = io4[q];
        float r[4] = {v.x, v.y, v.z, v.w};
        #pragma unroll
        for (int i = 0; i < 4; ++i) {
            float x = r[i];
            int j = (int)(x * 255.0f) + 1;
            j = min(max(j, 1), NBINS - 1);
            float2 c = C[j];
            r[i] = fminf(fmaxf(fmaf(c.x, x, c.y), LO), HI);
        }
        io4[q] = make_float4(r[0], r[1], r[2], r[3]);
    }
    for (int i = 4 * nq + blockIdx.x * blockDim.x + t; i < n; i += stride) {
        float x = io[i];
        int j = (int)(x * 255.0f) + 1;
        j = min(max(j, 1), NBINS - 1);
        float2 c = C[j];
        io[i] = fminf(fmaxf(fmaf(c.x, x, c.y), LO), HI);
    }
}

// ---------------------------------------------------------------------------
extern "C" void kernel_launch(void* const* d_in, const int* in_sizes, int n_in,
                              void* d_out, int out_size) {
    const float* src = (const float*)d_in[0];
    const float* tgt = (const float*)d_in[1];
    float* out = (float*)d_out;
    int n = in_sizes[0] / 3;   // H*W pixels
    int nq = n >> 2;

    cudaFuncSetAttribute(k1_hist, cudaFuncAttributeMaxDynamicSharedMemorySize,
                         J_BYTES);

    int ablocks = (nq + 255) / 256;
    if (ablocks > 888) ablocks = 888;
    if (ablocks < 1) ablocks = 1;

    k1_hist<<<H_BLK, H_TPB, J_BYTES>>>(src, tgt, out, n);
    k3_apply<<<ablocks, 256>>>(out, n);
}

// round 17
// speedup vs baseline: 1.0122x; 1.0122x over previous
#include <cuda_runtime.h>

#define NBINS   256
#define NSLOT   32
#define H_TPB   1024
#define H_BLK   148
#define J_BYTES (NBINS * NBINS * 2)      // 128 KB joint histogram (u16 cells)
#define CQ      14                       // px/CTA/chunk = 57344 < 65536
#define A_BLK   296                      // 2 CTAs/SM
#define A_TPB   256
#define A_ILP   4                        // quads per thread, loads batched

__device__ int   g_slots[2][NSLOT][NBINS];   // zero-init; last k1 block re-zeroes
__device__ float g_pxmap[NBINS];
__device__ int   g_done;

extern __shared__ unsigned int s_J[];

__device__ __forceinline__ int bin_of(float x) {
    return min(max((int)(x * 256.0f), 0), NBINS - 1);
}

__device__ __forceinline__ void jinc(int b, int c) {
    atomicAdd(&s_J[(b << 7) + (c >> 1)], 1u << ((c & 1) << 4));
}

// luma of rescaled pixel, folded: y = SC*(0.299r+0.587g+0.114b) + SC
__device__ __forceinline__ float luma(float r, float g, float b, float SC) {
    float dot = fmaf(0.299f, r, fmaf(0.587f, g, 0.114f * b));
    return fmaf(SC, dot, SC);
}

// ---------------------------------------------------------------------------
// k1: joint histogram + x spill to out + (last block) slot-reduce/CDF/pxmap.
// ---------------------------------------------------------------------------
__global__ void __launch_bounds__(H_TPB, 1) k1_hist(const float* __restrict__ src,
                                                    const float* __restrict__ tgt,
                                                    float* __restrict__ out, int n) {
    __shared__ int   sha[NBINS], shb[NBINS];
    __shared__ int   is_last;

    const int t    = threadIdx.x;
    const int nth  = gridDim.x * H_TPB;
    const int gtid = blockIdx.x * H_TPB + t;
    const int nq   = n >> 2;
    const float SC = 127.0f / 255.0f;
    const int CHUNK_Q = nth * CQ;

    if (t < NBINS) { sha[t] = 0; shb[t] = 0; }

    const float4* s4 = (const float4*)src;
    const float4* t4 = (const float4*)tgt;
    float4*       o4 = (float4*)out;

    for (int cbase = 0; cbase < nq; cbase += CHUNK_Q) {
        const int cend = min(cbase + CHUNK_Q, nq);

        {   // zero J
            uint4* z = (uint4*)s_J;
            #pragma unroll
            for (int i = 0; i < (NBINS * NBINS / 2 / 4) / H_TPB; ++i)
                z[t + i * H_TPB] = make_uint4(0, 0, 0, 0);
        }
        __syncthreads();

        for (int q = cbase + gtid; q < cend; q += nth) {
            float4 a  = s4[3 * q + 0];
            float4 b  = s4[3 * q + 1];
            float4 c  = s4[3 * q + 2];
            float4 ta = t4[3 * q + 0];
            float4 tb = t4[3 * q + 1];
            float4 tc = t4[3 * q + 2];

            float x0 = fmaf(a.x, SC, SC), x1 = fmaf(a.w, SC, SC);
            float x2 = fmaf(b.z, SC, SC), x3 = fmaf(c.y, SC, SC);
            o4[q] = make_float4(x0, x1, x2, x3);

            float y0 = luma(ta.x, ta.y, ta.z, SC);
            float y1 = luma(ta.w, tb.x, tb.y, SC);
            float y2 = luma(tb.z, tb.w, tc.x, SC);
            float y3 = luma(tc.y, tc.z, tc.w, SC);

            jinc(bin_of(x0), bin_of(y0));       // ONE atomic per pixel
            jinc(bin_of(x1), bin_of(y1));
            jinc(bin_of(x2), bin_of(y2));
            jinc(bin_of(x3), bin_of(y3));
        }
        __syncthreads();

        // ---- marginals ----
        if (t < NBINS) {
            const unsigned int* row = s_J + (t << 7);
            unsigned int s = 0;
            #pragma unroll 8
            for (int i = 0; i < 128; ++i) {
                unsigned int w = row[(i + t) & 127];   // +t swizzle: conflict-free
                s += (w & 0xffffu) + (w >> 16);
            }
            sha[t] += (int)s;
        } else if (t < 3 * NBINS) {
            const int u    = t - NBINS;
            const int c    = u >> 1;
            const int half = u & 1;
            const int widx = c >> 1;
            const int shft = (c & 1) << 4;
            unsigned int s = 0;
            #pragma unroll 8
            for (int b = half * 128; b < half * 128 + 128; ++b) {
                unsigned int w = s_J[(b << 7) + widx];
                s += (w >> shft) & 0xffffu;
            }
            if (s) atomicAdd(&shb[c], (int)s);
        }
        __syncthreads();
    }

    // Tail pixels (n % 4): at most 3, straight to global slot 0.
    const int tidx = 4 * nq + gtid;
    if (tidx < n) {
        float x = fmaf(src[3 * tidx], SC, SC);
        out[tidx] = x;
        atomicAdd(&g_slots[0][0][bin_of(x)], 1);
        float y = luma(tgt[3 * tidx + 0], tgt[3 * tidx + 1], tgt[3 * tidx + 2], SC);
        atomicAdd(&g_slots[1][0][bin_of(y)], 1);
    }

    // ---- slotted flush ----
    {
        const int slot = blockIdx.x & (NSLOT - 1);
        if (t < NBINS) {
            int va = sha[t];
            if (va) atomicAdd(&g_slots[0][slot][t], va);
        } else if (t < 2 * NBINS) {
            int vb = shb[t - NBINS];
            if (vb) atomicAdd(&g_slots[1][slot][t - NBINS], vb);
        }
    }

    // release flushes, then count this block done
    __threadfence();
    __syncthreads();
    if (t == 0)
        is_last = (atomicAdd(&g_done, 1) == (int)gridDim.x - 1);
    __syncthreads();
    if (!is_last) return;

    // ======== last block only: reduce slots, CDF, pxmap ========
    __threadfence();   // acquire: all other blocks' REDs visible
    __shared__ float fsv2[NBINS], ct[NBINS];
    if (t < NBINS) {
        float v = (float)((double)t * (1.0 / 255.0));  // np.arange semantics
        fsv2[t] = fminf(fmaxf(v, 0.0f), 1.0f);
        int suma = 0, sumb = 0;
        #pragma unroll
        for (int s = 0; s < NSLOT; ++s) {
            suma += g_slots[0][s][t];
            sumb += g_slots[1][s][t];
            g_slots[0][s][t] = 0;        // safe: all flushes counted above
            g_slots[1][s][t] = 0;
        }
        sha[t] = suma;
        shb[t] = sumb;
    }
    __syncthreads();
    #pragma unroll
    for (int off = 1; off < NBINS; off <<= 1) {
        int aself = 0, bself = 0, aprev = 0, bprev = 0;
        if (t < NBINS) {
            aself = sha[t]; bself = shb[t];
            if (t >= off) { aprev = sha[t - off]; bprev = shb[t - off]; }
        }
        __syncthreads();
        if (t < NBINS) { sha[t] = aself + aprev; shb[t] = bself + bprev; }
        __syncthreads();
    }
    if (t < NBINS) {
        int mint = shb[0];
        ct[t] = (float)(shb[t] - mint) / (float)(n - 1);      // cdftgt
    }
    __syncthreads();
    if (t < NBINS) {
        int mins = sha[0];
        float x = (float)(sha[t] - mins) / (float)(n - 1);    // cdfsrc
        int lo = 0, hi = NBINS - 1;
        while (lo < hi) { int mid = (lo + hi) >> 1; if (ct[mid] > x) hi = mid; else lo = mid + 1; }
        int ind1 = lo;
        int ind0 = max(ind1 - 1, 0);
        float dx0 = ct[ind0], dx1 = ct[ind1];
        float dy0 = fsv2[ind0], dy1 = fsv2[ind1];
        float dnm = dx1 - dx0;
        float sd  = (dnm == 0.0f) ? 1.0f : dnm;
        float interp = dy0 + (dy1 - dy0) * (x - dx0) / sd;
        float res = (x <= ct[0]) ? fsv2[0]
                  : ((x >= ct[NBINS - 1]) ? fsv2[NBINS - 1] : interp);
        g_pxmap[t] = res;
    }
    __syncthreads();
    if (t == 0) {
        g_done = 0;          // replay reset (all blocks already counted)
        __threadfence();
    }
}

// ---------------------------------------------------------------------------
// k3: apply with MLP=4 (all loads issued before compute), direct segment
// index + folded-clip float2 table (validated R16: rel_err 4.3e-7).
// ---------------------------------------------------------------------------
__global__ void __launch_bounds__(A_TPB, 2) k3_apply(float* __restrict__ io, int n) {
    __shared__ float2 C[NBINS];
    __shared__ float  fsv[NBINS], pmS[NBINS];
    const int t = threadIdx.x;
    const float K = 255.0f / 127.0f;

    {
        float v = (float)((double)t * (1.0 / 255.0));
        fsv[t] = fminf(fmaxf(v, 0.0f), 1.0f);
        pmS[t] = g_pxmap[t];
    }
    __syncthreads();
    if (t > 0) {
        float d = fsv[t] - fsv[t - 1];             // strictly > 0
        float a = (pmS[t] - pmS[t - 1]) / d;
        float b = pmS[t - 1] - a * fsv[t - 1];
        C[t] = make_float2(a * K, b * K - 1.0f);
    }
    __syncthreads();

    const float LO = -1.0f;
    const float HI = 255.0f / 127.0f - 1.0f;

    float4* io4 = (float4*)io;
    const int nq   = n >> 2;
    const int nth  = gridDim.x * A_TPB;
    const int gtid = blockIdx.x * A_TPB + t;

    for (int q0 = gtid; q0 < nq; q0 += A_ILP * nth) {
        float4 v[A_ILP];
        // batch all loads first -> MLP = A_ILP
        #pragma unroll
        for (int k = 0; k < A_ILP; ++k) {
            int q = q0 + k * nth;
            if (q < nq) v[k] = io4[q];
        }
        #pragma unroll
        for (int k = 0; k < A_ILP; ++k) {
            int q = q0 + k * nth;
            if (q < nq) {
                float r[4] = {v[k].x, v[k].y, v[k].z, v[k].w};
                #pragma unroll
                for (int i = 0; i < 4; ++i) {
                    float x = r[i];
                    int j = (int)(x * 255.0f) + 1;
                    j = min(max(j, 1), NBINS - 1);
                    float2 c = C[j];
                    r[i] = fminf(fmaxf(fmaf(c.x, x, c.y), LO), HI);
                }
                io4[q] = make_float4(r[0], r[1], r[2], r[3]);
            }
        }
    }
    for (int i = 4 * nq + gtid; i < n; i += nth) {
        float x = io[i];
        int j = (int)(x * 255.0f) + 1;
        j = min(max(j, 1), NBINS - 1);
        float2 c = C[j];
        io[i] = fminf(fmaxf(fmaf(c.x, x, c.y), LO), HI);
    }
}

// ---------------------------------------------------------------------------
extern "C" void kernel_launch(void* const* d_in, const int* in_sizes, int n_in,
                              void* d_out, int out_size) {
    const float* src = (const float*)d_in[0];
    const float* tgt = (const float*)d_in[1];
    float* out = (float*)d_out;
    int n = in_sizes[0] / 3;   // H*W pixels

    cudaFuncSetAttribute(k1_hist, cudaFuncAttributeMaxDynamicSharedMemorySize,
                         J_BYTES);

    k1_hist<<<H_BLK, H_TPB, J_BYTES>>>(src, tgt, out, n);
    k3_apply<<<A_BLK, A_TPB>>>(out, n);
}